// round 7
// baseline (speedup 1.0000x reference)
#include <cuda_runtime.h>
#include <cuda_fp16.h>
#include <cstdint>

// Problem dims
#define K_DIM 8192
#define N_DIM 8192

// GEMM tiling
#define KSPLIT 4
#define KCHUNK (K_DIM / KSPLIT)          // 2048
#define NKSTEPS (KCHUNK / 16)            // 128 k-steps of 16
#define CTA_N 128
#define NSTRIPS (N_DIM / CTA_N)          // 64
#define WARPS 8
#define WARP_N 16                        // 2 n-tiles of 8 per warp
#define STAGES 4

// Shared-memory stage layout
#define W_ROW_BYTES (CTA_N * 4)                  // 512
#define W_ROW_STRIDE (W_ROW_BYTES + 16)          // 528 (pad -> conflict-free frag LDS)
#define W_STAGE_BYTES (16 * W_ROW_STRIDE)        // 8448
#define A_STAGE_BYTES 1024                       // 2 t-tiles * 32 lanes * 16B
#define STAGE_BYTES (W_STAGE_BYTES + A_STAGE_BYTES)  // 9472
#define SMEM_BYTES (STAGES * STAGE_BYTES)        // 37888 (< 48KB static limit)

// Scratch (allocation-free: __device__ globals)
__device__ __align__(16) __half g_Apack[32 * K_DIM];    // 512 KB, fragment-packed A
__device__ float g_Yp[KSPLIT][32 * N_DIM];              // 4 MB partials
__device__ float g_corr[32];                            // 1152 * rowsum(fp16(x*s))

// ---------------------------------------------------------------------------
// Kernel 1: blocks [0,512): fold scaler into x, fp16, fragment-pack A.
//           blocks [512,544): per-batch-row bias-correction sums.
// ---------------------------------------------------------------------------
__global__ void prep_pack_kernel(const float* __restrict__ x,
                                 const float* __restrict__ scaler) {
    float s = scaler[0];
    if (blockIdx.x < 512) {
        int idx = blockIdx.x * blockDim.x + threadIdx.x;   // 0 .. 32*4096-1
        int r  = idx >> 12;          // A row 0..31
        int kp = idx & 4095;         // k pair index
        int k  = kp * 2;
        float xs0 = x[r * K_DIM + k] * s;
        float xs1 = x[r * K_DIM + k + 1] * s;
        __half2 h2 = __floats2half2_rn(xs0, xs1);          // low = xs0 (even k)
        unsigned packed = *reinterpret_cast<unsigned*>(&h2);
        // Fragment slot order {a0,a1,a2,a3} = {(g,klo),(g+8,klo),(g,khi),(g+8,khi)}
        int ks = k >> 4;
        int kk = k & 15;
        int t  = r >> 4;             // 0..1
        int gg = r & 15;
        int gq = gg & 7;
        int tg = (kk >> 1) & 3;
        int slot = ((kk >> 3) << 1) | (gg >> 3);
        size_t off = (size_t)ks * A_STAGE_BYTES + t * 512 + (gq * 4 + tg) * 16 + slot * 4;
        *(unsigned*)((char*)g_Apack + off) = packed;
    } else {
        // Correction: g_corr[row] = 1152 * sum_k fp16(x[row][k] * s)
        int row = blockIdx.x - 512;  // 0..31
        __shared__ float red[256];
        float acc = 0.0f;
        for (int k = threadIdx.x; k < K_DIM; k += 256) {
            __half h = __float2half_rn(x[row * K_DIM + k] * s);
            acc += __half2float(h);
        }
        red[threadIdx.x] = acc;
        __syncthreads();
        for (int off = 128; off > 0; off >>= 1) {
            if (threadIdx.x < off) red[threadIdx.x] += red[threadIdx.x + off];
            __syncthreads();
        }
        if (threadIdx.x == 0) g_corr[row] = 1152.0f * red[0];
    }
}

// ---------------------------------------------------------------------------
// Kernel 2: cp.async-pipelined fused dequant GEMM (mma m16n8k16 f16.f32).
// B conversion via integer bias trick: fp16bits(1152+w) = w + 0x6480 (low 16).
// ---------------------------------------------------------------------------
__global__ __launch_bounds__(256, 2) void gemm_kernel(const int* __restrict__ W) {
    __shared__ __align__(16) char sm[SMEM_BYTES];

    const int tid  = threadIdx.x;
    const int lane = tid & 31;
    const int warp = tid >> 5;
    const int g    = lane >> 2;
    const int tg   = lane & 3;

    const int n0cta = blockIdx.x * CTA_N;
    const int krow0 = blockIdx.y * KCHUNK;     // first k row of this split
    const int ks0   = blockIdx.y * NKSTEPS;    // first global kstep (for A pack)

    // cp.async thread coords: each thread copies two 16B W granules;
    // threads [0,64) also copy one 16B A granule.
    const int r0  = tid >> 5;                  // W tile row 0..7 (and +8)
    const int c16 = tid & 31;                  // 16B column granule within row
    const char* wsrc0 = (const char*)(W + (size_t)(krow0 + r0) * N_DIM + n0cta + c16 * 4);
    const char* asrc0 = (const char*)g_Apack + (size_t)ks0 * A_STAGE_BYTES + tid * 16;
    const unsigned sm_base = (unsigned)__cvta_generic_to_shared(sm);

    auto issue_stage = [&](int p) {
        if (p < NKSTEPS) {
            unsigned d  = sm_base + (p & (STAGES - 1)) * STAGE_BYTES;
            const char* ws = wsrc0 + (size_t)p * 16 * N_DIM * 4;
            unsigned d0 = d + r0 * W_ROW_STRIDE + c16 * 16;
            asm volatile("cp.async.cg.shared.global [%0], [%1], 16;\n"
                         :: "r"(d0), "l"(ws));
            asm volatile("cp.async.cg.shared.global [%0], [%1], 16;\n"
                         :: "r"(d0 + 8 * W_ROW_STRIDE), "l"(ws + (size_t)8 * N_DIM * 4));
            if (tid < 64) {
                asm volatile("cp.async.ca.shared.global [%0], [%1], 16;\n"
                             :: "r"(d + W_STAGE_BYTES + tid * 16),
                                "l"(asrc0 + (size_t)p * A_STAGE_BYTES));
            }
        }
        asm volatile("cp.async.commit_group;\n" ::);
    };

    issue_stage(0);
    issue_stage(1);
    issue_stage(2);

    float acc[2][2][4] = {};

    for (int ks = 0; ks < NKSTEPS; ks++) {
        asm volatile("cp.async.wait_group 2;\n" ::);
        __syncthreads();
        issue_stage(ks + 3);   // refills the buffer consumed at iteration ks-1

        const unsigned sb = sm_base + (ks & (STAGES - 1)) * STAGE_BYTES;

        // A fragments: 2 x LDS.128 (broadcast across warps)
        unsigned a[2][4];
        const unsigned ab = sb + W_STAGE_BYTES + lane * 16;
        #pragma unroll
        for (int t = 0; t < 2; t++) {
            asm volatile("ld.shared.v4.b32 {%0,%1,%2,%3}, [%4];"
                         : "=r"(a[t][0]), "=r"(a[t][1]), "=r"(a[t][2]), "=r"(a[t][3])
                         : "r"(ab + t * 512));
        }

        #pragma unroll
        for (int i = 0; i < 2; i++) {
            // B ints from smem: rows tg*2 + {0,1,8,9}, col warp*16 + i*8 + g.
            // bank = 8*tg + g (+16*warp) : conflict-free.
            const unsigned wb = sb + (tg * 2) * W_ROW_STRIDE + (warp * WARP_N + i * 8 + g) * 4;
            int w0, w1, w2, w3;
            asm volatile("ld.shared.b32 %0, [%1];" : "=r"(w0) : "r"(wb));
            asm volatile("ld.shared.b32 %0, [%1];" : "=r"(w1) : "r"(wb + W_ROW_STRIDE));
            asm volatile("ld.shared.b32 %0, [%1];" : "=r"(w2) : "r"(wb + 8 * W_ROW_STRIDE));
            asm volatile("ld.shared.b32 %0, [%1];" : "=r"(w3) : "r"(wb + 9 * W_ROW_STRIDE));
            // fp16 bits of (1152 + w) = w + 0x6480 (low 16 bits); pack pairs.
            unsigned v0 = (unsigned)(w0 + 0x6480);
            unsigned v1 = (unsigned)(w1 + 0x6480);
            unsigned v2 = (unsigned)(w2 + 0x6480);
            unsigned v3 = (unsigned)(w3 + 0x6480);
            unsigned b0 = __byte_perm(v0, v1, 0x5410);   // low = even k
            unsigned b1 = __byte_perm(v2, v3, 0x5410);

            #pragma unroll
            for (int t = 0; t < 2; t++) {
                float* c = acc[t][i];
                asm volatile(
                    "mma.sync.aligned.m16n8k16.row.col.f32.f16.f16.f32 "
                    "{%0,%1,%2,%3}, {%4,%5,%6,%7}, {%8,%9}, {%0,%1,%2,%3};"
                    : "+f"(c[0]), "+f"(c[1]), "+f"(c[2]), "+f"(c[3])
                    : "r"(a[t][0]), "r"(a[t][1]), "r"(a[t][2]), "r"(a[t][3]),
                      "r"(b0), "r"(b1));
            }
        }
    }

    // Epilogue: fp32 partials (bias still included; removed in reduce)
    float* yp = g_Yp[blockIdx.y];
    #pragma unroll
    for (int t = 0; t < 2; t++) {
        #pragma unroll
        for (int i = 0; i < 2; i++) {
            const int row = t * 16 + g;
            const int col = n0cta + warp * WARP_N + i * 8 + tg * 2;
            *reinterpret_cast<float2*>(&yp[(size_t)row * N_DIM + col]) =
                make_float2(acc[t][i][0], acc[t][i][1]);
            *reinterpret_cast<float2*>(&yp[(size_t)(row + 8) * N_DIM + col]) =
                make_float2(acc[t][i][2], acc[t][i][3]);
        }
    }
}

// ---------------------------------------------------------------------------
// Kernel 3: reduce k-splits, subtract bias correction.
// ---------------------------------------------------------------------------
__global__ void reduce_kernel(float* __restrict__ out) {
    int idx = blockIdx.x * blockDim.x + threadIdx.x;   // 0 .. 32*8192-1
    int b = idx >> 13;
    float s = -g_corr[b];
    #pragma unroll
    for (int sp = 0; sp < KSPLIT; sp++)
        s += g_Yp[sp][idx];
    out[idx] = s;
}

// ---------------------------------------------------------------------------
extern "C" void kernel_launch(void* const* d_in, const int* in_sizes, int n_in,
                              void* d_out, int out_size) {
    const float* x      = (const float*)d_in[0];   // [32, 8192] fp32
    const int*   w      = (const int*)d_in[1];     // [8192, 8192] int32 (int8-valued)
    const float* scaler = (const float*)d_in[2];   // [1] fp32
    float* out = (float*)d_out;                    // [32, 8192] fp32

    prep_pack_kernel<<<544, 256>>>(x, scaler);
    gemm_kernel<<<dim3(NSTRIPS, KSPLIT), 256>>>(w);
    reduce_kernel<<<512, 512>>>(out);
}